// round 4
// baseline (speedup 1.0000x reference)
#include <cuda_runtime.h>
#include <cuda_bf16.h>

// EquiConv fused kernel.
// Shapes: E=20000, S=64, V=32, FC_IN=128, HID=64.
// out[e] = concat( silu(sc)*w[:64] , (vec * sigmoid(g) * w[64:96]).reshape(96) )

#define S_DIM 64
#define V_DIM 32
#define TE 8          // edges per block
#define NTHREADS 256

#define INV_SQRT3_F 0.5773502691896258f
#define A_SC_F 0.013975424859373686f   // 1/sqrt(64*64+32*32)
#define A_VEC_F 0.015625f              // 1/sqrt(2*64*32)

__device__ __forceinline__ float sigmoidf_(float x) {
    return 1.0f / (1.0f + expf(-x));
}

__global__ __launch_bounds__(NTHREADS) void equiconv_kernel(
    const float* __restrict__ fea_in1,
    const float* __restrict__ fea_in2,
    const float* __restrict__ fea_weight,
    const float* __restrict__ wsss,   // (64,64,64)
    const float* __restrict__ wvvs,   // (32,32,64)
    const float* __restrict__ wssg,   // (64,64,32)
    const float* __restrict__ wvvg,   // (32,32,32)
    const float* __restrict__ wsvv,   // (64,32,32)
    const float* __restrict__ wvsv,   // (32,64,32)
    const float* __restrict__ fw1,    // (128,64)
    const float* __restrict__ fb1,    // (64)
    const float* __restrict__ fw2,    // (64,64)
    const float* __restrict__ fb2,    // (64)
    const float* __restrict__ fw3,    // (64,96)
    const float* __restrict__ fb3,    // (96)
    float* __restrict__ out)          // (E,160)
{
    __shared__ float s_x1s[TE * 64];
    __shared__ float s_x2s[TE * 64];
    __shared__ float s_x1v[TE * 96];
    __shared__ float s_x2v[TE * 96];
    __shared__ float s_wout[TE * 96];
    __shared__ float s_sig[TE * 32];
    // union region: MLP buffers first (fw 1024 + h1 512 + h2 512), then Q (8192)
    __shared__ float s_un[TE * 1024];

    const int tid = threadIdx.x;
    const int e0 = blockIdx.x * TE;

    // ---- Phase 1: stage edge features ----
    for (int idx = tid; idx < TE * 160; idx += NTHREADS) {
        int e = idx / 160;
        int c = idx - e * 160;
        float v1 = fea_in1[(long)e0 * 160 + idx];
        float v2 = fea_in2[(long)e0 * 160 + idx];
        if (c < 64) {
            s_x1s[e * 64 + c] = v1;
            s_x2s[e * 64 + c] = v2;
        } else {
            s_x1v[e * 96 + (c - 64)] = v1;
            s_x2v[e * 96 + (c - 64)] = v2;
        }
    }
    float* s_fw = s_un;             // TE*128
    float* s_h1 = s_un + TE * 128;  // TE*64
    float* s_h2 = s_un + TE * 192;  // TE*64
    for (int idx = tid; idx < TE * 128; idx += NTHREADS)
        s_fw[idx] = fea_weight[(long)e0 * 128 + idx];
    __syncthreads();

    // ---- Phase 2: MLP ----
    for (int idx = tid; idx < TE * 64; idx += NTHREADS) {
        int e = idx >> 6, j = idx & 63;
        float acc = fb1[j];
        const float* xe = &s_fw[e * 128];
        #pragma unroll 8
        for (int k = 0; k < 128; k++) acc += xe[k] * fw1[k * 64 + j];
        s_h1[idx] = acc * sigmoidf_(acc);
    }
    __syncthreads();
    for (int idx = tid; idx < TE * 64; idx += NTHREADS) {
        int e = idx >> 6, j = idx & 63;
        float acc = fb2[j];
        const float* xe = &s_h1[e * 64];
        #pragma unroll 8
        for (int k = 0; k < 64; k++) acc += xe[k] * fw2[k * 64 + j];
        s_h2[idx] = acc * sigmoidf_(acc);
    }
    __syncthreads();
    for (int idx = tid; idx < TE * 96; idx += NTHREADS) {
        int e = idx / 96, j = idx - e * 96;
        float acc = fb3[j];
        const float* xe = &s_h2[e * 64];
        #pragma unroll 8
        for (int k = 0; k < 64; k++) acc += xe[k] * fw3[k * 96 + j];
        s_wout[idx] = acc;
    }
    __syncthreads();

    // ---- Phase 3: Q[e][u][v] = INV_SQRT3 * dot3(x1v[u], x2v[v]) ----
    for (int idx = tid; idx < TE * 1024; idx += NTHREADS) {
        int e = idx >> 10;
        int u = (idx >> 5) & 31;
        int v = idx & 31;
        const float* a = &s_x1v[e * 96 + u * 3];
        const float* b = &s_x2v[e * 96 + v * 3];
        s_un[idx] = INV_SQRT3_F * (a[0] * b[0] + a[1] * b[1] + a[2] * b[2]);
    }
    __syncthreads();

    // ---- Phase 4: sc (64 outputs) and g (32 outputs) per edge ----
    {
        const int wp = tid & 31;   // w-pair index: handles w = 2wp, 2wp+1
        const int e = tid >> 5;    // edge within tile
        const bool do_g = wp < 16; // g-pair index: gw = 2wp, 2wp+1 (wp<16)
        const float* x1 = &s_x1s[e * 64];
        const float* x2 = &s_x2s[e * 64];
        const float2* wsss2 = (const float2*)wsss;
        const float2* wssg2 = (const float2*)wssg;
        const float2* wvvs2 = (const float2*)wvvs;
        const float2* wvvg2 = (const float2*)wvvg;

        float s0 = 0.f, s1 = 0.f, g0 = 0.f, g1 = 0.f;

        // ss contraction: P[u,v] = x1s[u]*x2s[v]
        for (int u = 0; u < 64; u++) {
            float a = x1[u];
            const float2* wrow = wsss2 + u * 2048 + wp;  // (u*64+v)*32 + wp
            const float2* grow = wssg2 + u * 1024 + wp;  // (u*64+v)*16 + wp
            #pragma unroll 4
            for (int v = 0; v < 64; v++) {
                float p = a * x2[v];
                float2 wt = wrow[v * 32];
                s0 += p * wt.x;
                s1 += p * wt.y;
                if (do_g) {
                    float2 wg = grow[v * 16];
                    g0 += p * wg.x;
                    g1 += p * wg.y;
                }
            }
        }
        // vv contraction with pre-scaled Q
        {
            const float* Qe = &s_un[e * 1024];
            for (int u = 0; u < 32; u++) {
                const float2* wrow = wvvs2 + u * 1024 + wp;  // (u*32+v)*32 + wp
                const float2* grow = wvvg2 + u * 512 + wp;   // (u*32+v)*16 + wp
                const float* qrow = Qe + u * 32;
                #pragma unroll 4
                for (int v = 0; v < 32; v++) {
                    float q = qrow[v];
                    float2 wt = wrow[v * 32];
                    s0 += q * wt.x;
                    s1 += q * wt.y;
                    if (do_g) {
                        float2 wg = grow[v * 16];
                        g0 += q * wg.x;
                        g1 += q * wg.y;
                    }
                }
            }
        }

        int w0 = 2 * wp, w1 = w0 + 1;
        s0 *= A_SC_F;
        s1 *= A_SC_F;
        float o0 = s0 * sigmoidf_(s0) * s_wout[e * 96 + w0];
        float o1 = s1 * sigmoidf_(s1) * s_wout[e * 96 + w1];
        long base = (long)(e0 + e) * 160;
        out[base + w0] = o0;
        out[base + w1] = o1;
        if (do_g) {
            g0 *= A_SC_F;
            g1 *= A_SC_F;
            s_sig[e * 32 + w0] = sigmoidf_(g0);
            s_sig[e * 32 + w1] = sigmoidf_(g1);
        }
    }
    __syncthreads();

    // ---- Phase 5: vec (32 w-outputs x 3 components) per edge ----
    {
        const int w = tid & 31;
        const int e = tid >> 5;
        const float* x1s_e = &s_x1s[e * 64];
        const float* x2s_e = &s_x2s[e * 64];
        const float* x1v_e = &s_x1v[e * 96];
        const float* x2v_e = &s_x2v[e * 96];

        float a0 = 0.f, a1 = 0.f, a2 = 0.f;

        // sv: y[w,i] = sum_v x2v[v,i] * ( sum_u x1s[u] * wsvv[u,v,w] )
        for (int v = 0; v < V_DIM; v++) {
            float bv = 0.f;
            const float* wcol = wsvv + v * 32 + w;  // (u*32+v)*32+w, u-stride 1024
            #pragma unroll 8
            for (int u = 0; u < 64; u++) bv += x1s_e[u] * wcol[u * 1024];
            a0 += bv * x2v_e[v * 3 + 0];
            a1 += bv * x2v_e[v * 3 + 1];
            a2 += bv * x2v_e[v * 3 + 2];
        }
        // vs: y[w,i] = sum_u x1v[u,i] * ( sum_v x2s[v] * wvsv[u,v,w] )
        for (int u = 0; u < V_DIM; u++) {
            float cu = 0.f;
            const float* wrow = wvsv + u * 2048 + w;  // (u*64+v)*32+w, v-stride 32
            #pragma unroll 8
            for (int v = 0; v < 64; v++) cu += x2s_e[v] * wrow[v * 32];
            a0 += cu * x1v_e[u * 3 + 0];
            a1 += cu * x1v_e[u * 3 + 1];
            a2 += cu * x1v_e[u * 3 + 2];
        }

        float m = A_VEC_F * s_sig[e * 32 + w] * s_wout[e * 96 + 64 + w];
        long base = (long)(e0 + e) * 160 + 64 + w * 3;
        out[base + 0] = a0 * m;
        out[base + 1] = a1 * m;
        out[base + 2] = a2 * m;
    }
}

extern "C" void kernel_launch(void* const* d_in, const int* in_sizes, int n_in,
                              void* d_out, int out_size) {
    (void)in_sizes; (void)n_in; (void)out_size;
    const float* fea_in1    = (const float*)d_in[0];
    const float* fea_in2    = (const float*)d_in[1];
    const float* fea_weight = (const float*)d_in[2];
    const float* w_ss_s     = (const float*)d_in[3];
    const float* w_vv_s     = (const float*)d_in[4];
    const float* w_ss_g     = (const float*)d_in[5];
    const float* w_vv_g     = (const float*)d_in[6];
    const float* w_sv_v     = (const float*)d_in[7];
    const float* w_vs_v     = (const float*)d_in[8];
    const float* fc_w1      = (const float*)d_in[9];
    const float* fc_b1      = (const float*)d_in[10];
    const float* fc_w2      = (const float*)d_in[11];
    const float* fc_b2      = (const float*)d_in[12];
    const float* fc_w3      = (const float*)d_in[13];
    const float* fc_b3      = (const float*)d_in[14];
    // d_in[15] = batch_edge (unused)
    float* out = (float*)d_out;

    const int E = 20000;
    dim3 grid(E / TE);
    dim3 block(NTHREADS);
    equiconv_kernel<<<grid, block>>>(
        fea_in1, fea_in2, fea_weight,
        w_ss_s, w_vv_s, w_ss_g, w_vv_g, w_sv_v, w_vs_v,
        fc_w1, fc_b1, fc_w2, fc_b2, fc_w3, fc_b3,
        out);
}

// round 5
// speedup vs baseline: 1.6994x; 1.6994x over previous
#include <cuda_runtime.h>
#include <cuda_bf16.h>

// EquiConv fused kernel, GEMM-restructured.
// E=20000, S=64, V=32, FC_IN=128, HID=64. out (E,160).
// sc/g: [sc|g](e, 0:96) = sum_k P[e,k] * Wcat[k, 0:96], K = 4096 (ss) + 1024 (vv).
// vec: factored  B1[e,v,w] = sum_u x1s*wsvv ; B2[e,u,w] = sum_v x2s*wvsv, folded with x2v/x1v.

#define TE 16      // edges per block (20000 / 16 = 1250 blocks exactly)
#define NT 256
#define KC 32      // K chunk

#define INV_SQRT3_F 0.5773502691896258f
#define A_SC_F 0.013975424859373686f   // 1/sqrt(64*64+32*32)
#define A_VEC_F 0.015625f              // 1/sqrt(2*64*32)

__device__ __forceinline__ float sigmoidf_(float x) {
    return 1.0f / (1.0f + expf(-x));
}

__global__ __launch_bounds__(NT, 4) void equiconv_kernel(
    const float* __restrict__ fea_in1,
    const float* __restrict__ fea_in2,
    const float* __restrict__ fea_weight,
    const float* __restrict__ wsss,   // (64,64,64)  flat: k*64 + w   (k = u*64+v)
    const float* __restrict__ wvvs,   // (32,32,64)  flat: k2*64 + w  (k2 = u*32+v)
    const float* __restrict__ wssg,   // (64,64,32)  flat: k*32 + g
    const float* __restrict__ wvvg,   // (32,32,32)
    const float* __restrict__ wsvv,   // (64,32,32)  u*1024 + v*32 + w
    const float* __restrict__ wvsv,   // (32,64,32)  u*2048 + v*32 + w
    const float* __restrict__ fw1, const float* __restrict__ fb1,
    const float* __restrict__ fw2, const float* __restrict__ fb2,
    const float* __restrict__ fw3, const float* __restrict__ fb3,
    float* __restrict__ out)
{
    __shared__ float s_x1s[TE * 65];   // padded stride 65 (bank conflicts)
    __shared__ float s_x2s[TE * 65];
    __shared__ float s_x1v[TE * 97];   // padded stride 97
    __shared__ float s_x2v[TE * 97];
    __shared__ float s_wout[TE * 96];
    __shared__ float s_sig[TE * 32];
    __shared__ float s_un[4096];       // 16KB union: MLP bufs / Wchunk+Pchunk / vec weight chunk

    const int tid  = threadIdx.x;
    const int wid  = tid >> 5;         // warp owns edges 2*wid, 2*wid+1
    const int lane = tid & 31;         // lane owns w-cols {lane, lane+32, lane+64}
    const int e0g  = blockIdx.x * TE;

    // ---- stage edge features ----
    for (int idx = tid; idx < TE * 160; idx += NT) {
        int e = idx / 160;
        int c = idx - e * 160;
        float v1 = fea_in1[e0g * 160 + idx];
        float v2 = fea_in2[e0g * 160 + idx];
        if (c < 64) { s_x1s[e * 65 + c] = v1; s_x2s[e * 65 + c] = v2; }
        else        { s_x1v[e * 97 + (c - 64)] = v1; s_x2v[e * 97 + (c - 64)] = v2; }
    }
    float* s_fw = s_un;              // 16*128
    float* s_h1 = s_un + 2048;       // 16*64
    float* s_h2 = s_un + 3072;       // 16*64
    for (int idx = tid; idx < TE * 128; idx += NT)
        s_fw[idx] = fea_weight[e0g * 128 + idx];
    __syncthreads();

    // ---- MLP -> s_wout ----
    #pragma unroll
    for (int it = 0; it < 4; it++) {
        int o = tid + NT * it; int e = o >> 6, j = o & 63;
        float acc = fb1[j];
        const float* xe = s_fw + e * 128;
        #pragma unroll 8
        for (int k = 0; k < 128; k++) acc += xe[k] * fw1[k * 64 + j];
        s_h1[o] = acc * sigmoidf_(acc);
    }
    __syncthreads();
    #pragma unroll
    for (int it = 0; it < 4; it++) {
        int o = tid + NT * it; int e = o >> 6, j = o & 63;
        float acc = fb2[j];
        const float* xe = s_h1 + e * 64;
        #pragma unroll 8
        for (int k = 0; k < 64; k++) acc += xe[k] * fw2[k * 64 + j];
        s_h2[o] = acc * sigmoidf_(acc);
    }
    __syncthreads();
    #pragma unroll
    for (int it = 0; it < 6; it++) {
        int o = tid + NT * it; int e = o / 96, j = o - e * 96;
        float acc = fb3[j];
        const float* xe = s_h2 + e * 64;
        #pragma unroll 8
        for (int k = 0; k < 64; k++) acc += xe[k] * fw3[k * 96 + j];
        s_wout[o] = acc;
    }

    // ---- main GEMM: sc/g, K = 5120 in 160 chunks of 32 ----
    float a00 = 0.f, a01 = 0.f, a02 = 0.f;   // edge a: w=lane, lane+32, g=lane
    float a10 = 0.f, a11 = 0.f, a12 = 0.f;   // edge b
    float* Wc = s_un;          // [KC][96]
    float* Pc = s_un + 3072;   // [KC][16]

    for (int ci = 0; ci < 160; ci++) {
        __syncthreads();
        const int k0 = ci * KC;
        const bool ssr = (ci < 128);
        const float* baseS = ssr ? (wsss + k0 * 64) : (wvvs + (k0 - 4096) * 64);
        const float* baseG = ssr ? (wssg + k0 * 32) : (wvvg + (k0 - 4096) * 32);

        // stage W[:, 0:64]  (512 float4)
        #pragma unroll
        for (int i = 0; i < 2; i++) {
            int idx = tid + NT * i;
            int row = idx >> 4, c4 = idx & 15;
            float4 w4 = *(const float4*)(baseS + row * 64 + c4 * 4);
            *(float4*)(Wc + row * 96 + c4 * 4) = w4;
        }
        // stage W[:, 64:96] (256 float4)
        {
            int row = tid >> 3, c4 = tid & 7;
            float4 w4 = *(const float4*)(baseG + row * 32 + c4 * 4);
            *(float4*)(Wc + row * 96 + 64 + c4 * 4) = w4;
        }
        // generate P[kk][e]
        #pragma unroll
        for (int i = 0; i < 2; i++) {
            int idx = tid + NT * i;            // 512 values
            int kk = idx >> 4, e = idx & 15;
            int kg = k0 + kk;
            float p;
            if (ssr) {
                int u = kg >> 6, v = kg & 63;
                p = s_x1s[e * 65 + u] * s_x2s[e * 65 + v];
            } else {
                int k2 = kg - 4096;
                int u = k2 >> 5, v = k2 & 31;
                const float* av = s_x1v + e * 97 + u * 3;
                const float* bv = s_x2v + e * 97 + v * 3;
                p = INV_SQRT3_F * (av[0] * bv[0] + av[1] * bv[1] + av[2] * bv[2]);
            }
            Pc[kk * 16 + e] = p;
        }
        __syncthreads();

        const float* wp = Wc + lane;
        const float* pp = Pc + 2 * wid;
        #pragma unroll 8
        for (int kk = 0; kk < KC; kk++) {
            float2 p = *(const float2*)(pp + kk * 16);   // broadcast LDS.64
            float w0 = wp[kk * 96];
            float w1 = wp[kk * 96 + 32];
            float w2 = wp[kk * 96 + 64];
            a00 += p.x * w0; a01 += p.x * w1; a02 += p.x * w2;
            a10 += p.y * w0; a11 += p.y * w1; a12 += p.y * w2;
        }
    }

    // ---- sc/g epilogue ----
    const int ea = 2 * wid, eb = ea + 1;
    {
        float s;
        s = A_SC_F * a00; out[(long)(e0g + ea) * 160 + lane]      = s * sigmoidf_(s) * s_wout[ea * 96 + lane];
        s = A_SC_F * a01; out[(long)(e0g + ea) * 160 + lane + 32] = s * sigmoidf_(s) * s_wout[ea * 96 + lane + 32];
        s = A_SC_F * a10; out[(long)(e0g + eb) * 160 + lane]      = s * sigmoidf_(s) * s_wout[eb * 96 + lane];
        s = A_SC_F * a11; out[(long)(e0g + eb) * 160 + lane + 32] = s * sigmoidf_(s) * s_wout[eb * 96 + lane + 32];
        s_sig[ea * 32 + lane] = sigmoidf_(A_SC_F * a02);
        s_sig[eb * 32 + lane] = sigmoidf_(A_SC_F * a12);
    }

    // ---- vec: factored GEMMs with staged weight chunks ----
    float v00 = 0.f, v01 = 0.f, v02 = 0.f;   // edge a, components 0..2 (w = lane)
    float v10 = 0.f, v11 = 0.f, v12 = 0.f;   // edge b

    // sv:  B1[e,v,w] = sum_u x1s[e,u]*wsvv[u,v,w];  vec += B1 * x2v[e,v,i]
    for (int vc = 0; vc < 16; vc++) {
        __syncthreads();
        int v0 = vc * 2;
        #pragma unroll
        for (int i = 0; i < 4; i++) {
            int fidx = tid + NT * i;      // 1024 float4 = [128 rows][32]
            int r = fidx >> 3, c4 = fidx & 7;
            int u = r >> 1, vv = r & 1;
            *(float4*)(s_un + r * 32 + c4 * 4) =
                *(const float4*)(wsvv + u * 1024 + (v0 + vv) * 32 + c4 * 4);
        }
        __syncthreads();
        float b00 = 0.f, b01 = 0.f, b10 = 0.f, b11 = 0.f;  // [vv][edge]
        const float* wv = s_un + lane;
        #pragma unroll 8
        for (int u = 0; u < 64; u++) {
            float xa = s_x1s[ea * 65 + u];
            float xb = s_x1s[eb * 65 + u];
            float w0 = wv[(u * 2 + 0) * 32];
            float w1 = wv[(u * 2 + 1) * 32];
            b00 += xa * w0; b10 += xb * w0;
            b01 += xa * w1; b11 += xb * w1;
        }
        const float* xa = s_x2v + ea * 97 + v0 * 3;
        const float* xb = s_x2v + eb * 97 + v0 * 3;
        v00 += b00 * xa[0]; v01 += b00 * xa[1]; v02 += b00 * xa[2];
        v00 += b01 * xa[3]; v01 += b01 * xa[4]; v02 += b01 * xa[5];
        v10 += b10 * xb[0]; v11 += b10 * xb[1]; v12 += b10 * xb[2];
        v10 += b11 * xb[3]; v11 += b11 * xb[4]; v12 += b11 * xb[5];
    }

    // vs:  B2[e,u,w] = sum_v x2s[e,v]*wvsv[u,v,w];  vec += B2 * x1v[e,u,i]
    for (int uc = 0; uc < 16; uc++) {
        __syncthreads();
        int u0 = uc * 2;
        #pragma unroll
        for (int i = 0; i < 4; i++) {
            int fidx = tid + NT * i;      // [128 rows][32]: row = uu*64 + v
            int r = fidx >> 3, c4 = fidx & 7;
            int uu = r >> 6, v = r & 63;
            *(float4*)(s_un + r * 32 + c4 * 4) =
                *(const float4*)(wvsv + (u0 + uu) * 2048 + v * 32 + c4 * 4);
        }
        __syncthreads();
        float b00 = 0.f, b01 = 0.f, b10 = 0.f, b11 = 0.f;  // [uu][edge]
        const float* wv = s_un + lane;
        #pragma unroll 8
        for (int v = 0; v < 64; v++) {
            float xa = s_x2s[ea * 65 + v];
            float xb = s_x2s[eb * 65 + v];
            float w0 = wv[v * 32];
            float w1 = wv[(64 + v) * 32];
            b00 += xa * w0; b10 += xb * w0;
            b01 += xa * w1; b11 += xb * w1;
        }
        const float* xa = s_x1v + ea * 97 + u0 * 3;
        const float* xb = s_x1v + eb * 97 + u0 * 3;
        v00 += b00 * xa[0]; v01 += b00 * xa[1]; v02 += b00 * xa[2];
        v00 += b01 * xa[3]; v01 += b01 * xa[4]; v02 += b01 * xa[5];
        v10 += b10 * xb[0]; v11 += b10 * xb[1]; v12 += b10 * xb[2];
        v10 += b11 * xb[3]; v11 += b11 * xb[4]; v12 += b11 * xb[5];
    }

    // ---- vec epilogue ----
    {
        float ma = A_VEC_F * s_sig[ea * 32 + lane] * s_wout[ea * 96 + 64 + lane];
        float mb = A_VEC_F * s_sig[eb * 32 + lane] * s_wout[eb * 96 + 64 + lane];
        float* oa = out + (long)(e0g + ea) * 160 + 64 + lane * 3;
        float* ob = out + (long)(e0g + eb) * 160 + 64 + lane * 3;
        oa[0] = v00 * ma; oa[1] = v01 * ma; oa[2] = v02 * ma;
        ob[0] = v10 * mb; ob[1] = v11 * mb; ob[2] = v12 * mb;
    }
}

extern "C" void kernel_launch(void* const* d_in, const int* in_sizes, int n_in,
                              void* d_out, int out_size) {
    (void)in_sizes; (void)n_in; (void)out_size;
    const float* fea_in1    = (const float*)d_in[0];
    const float* fea_in2    = (const float*)d_in[1];
    const float* fea_weight = (const float*)d_in[2];
    const float* w_ss_s     = (const float*)d_in[3];
    const float* w_vv_s     = (const float*)d_in[4];
    const float* w_ss_g     = (const float*)d_in[5];
    const float* w_vv_g     = (const float*)d_in[6];
    const float* w_sv_v     = (const float*)d_in[7];
    const float* w_vs_v     = (const float*)d_in[8];
    const float* fc_w1      = (const float*)d_in[9];
    const float* fc_b1      = (const float*)d_in[10];
    const float* fc_w2      = (const float*)d_in[11];
    const float* fc_b2      = (const float*)d_in[12];
    const float* fc_w3      = (const float*)d_in[13];
    const float* fc_b3      = (const float*)d_in[14];
    float* out = (float*)d_out;

    // Maximize shared-memory carveout so 4 blocks/SM can co-reside.
    cudaFuncSetAttribute(equiconv_kernel,
                         cudaFuncAttributePreferredSharedMemoryCarveout,
                         cudaSharedmemCarveoutMaxShared);

    const int E = 20000;
    dim3 grid(E / TE);
    dim3 block(NT);
    equiconv_kernel<<<grid, block>>>(
        fea_in1, fea_in2, fea_weight,
        w_ss_s, w_vv_s, w_ss_g, w_vv_g, w_sv_v, w_vs_v,
        fc_w1, fc_b1, fc_w2, fc_b2, fc_w3, fc_b3,
        out);
}

// round 9
// speedup vs baseline: 2.3092x; 1.3589x over previous
#include <cuda_runtime.h>
#include <cuda_bf16.h>

// EquiConv fused kernel, GEMM-restructured, 4 edges/warp register blocking.
// E=20000, S=64, V=32, FC_IN=128, HID=64. out (E,160).

#define TE 32      // edges per block (20000/32 = 625 blocks exactly)
#define NT 256
#define KC 32      // K chunk

#define INV_SQRT3_F 0.5773502691896258f
#define A_SC_F 0.013975424859373686f   // 1/sqrt(64*64+32*32)
#define A_VEC_F 0.015625f              // 1/sqrt(2*64*32)

// shared layout (floats), all 16B-aligned offsets
#define OFF_X1ST 0                 // [64][36]  transposed x1s
#define OFF_X2ST 2304              // [64][36]
#define OFF_X1V  4608              // [32][97]
#define OFF_X2V  7712              // [32][97]
#define OFF_WOUT 10816             // [32][96]
#define OFF_SIG  13888             // [32][32]
#define OFF_UN   14912             // 4096 union: {MLP fw/h2} / {Wc 3072 + Pc 1024} / {vec 4096}
#define SMEM_FLOATS 19008          // 76032 bytes

__device__ __forceinline__ float sigmoidf_(float x) {
    return 1.0f / (1.0f + expf(-x));
}

__global__ __launch_bounds__(NT, 3) void equiconv_kernel(
    const float* __restrict__ fea_in1,
    const float* __restrict__ fea_in2,
    const float* __restrict__ fea_weight,
    const float* __restrict__ wsss,   // (64,64,64)  k*64 + w   (k = u*64+v)
    const float* __restrict__ wvvs,   // (32,32,64)
    const float* __restrict__ wssg,   // (64,64,32)
    const float* __restrict__ wvvg,   // (32,32,32)
    const float* __restrict__ wsvv,   // (64,32,32)  u*1024 + v*32 + w
    const float* __restrict__ wvsv,   // (32,64,32)  u*2048 + v*32 + w
    const float* __restrict__ fw1, const float* __restrict__ fb1,
    const float* __restrict__ fw2, const float* __restrict__ fb2,
    const float* __restrict__ fw3, const float* __restrict__ fb3,
    float* __restrict__ out)
{
    extern __shared__ float smem[];
    float* s_x1sT = smem + OFF_X1ST;
    float* s_x2sT = smem + OFF_X2ST;
    float* s_x1v  = smem + OFF_X1V;
    float* s_x2v  = smem + OFF_X2V;
    float* s_wout = smem + OFF_WOUT;
    float* s_sig  = smem + OFF_SIG;
    float* s_un   = smem + OFF_UN;

    const int tid  = threadIdx.x;
    const int wid  = tid >> 5;
    const int lane = tid & 31;
    const int e4   = 4 * wid;          // warp owns edges e4..e4+3
    const int e0g  = blockIdx.x * TE;

    // ---- stage edge features (scalars transposed) ----
    for (int idx = tid; idx < TE * 160; idx += NT) {
        int e = idx / 160;
        int c = idx - e * 160;
        float v1 = fea_in1[e0g * 160 + idx];
        float v2 = fea_in2[e0g * 160 + idx];
        if (c < 64) { s_x1sT[c * 36 + e] = v1; s_x2sT[c * 36 + e] = v2; }
        else        { s_x1v[e * 97 + (c - 64)] = v1; s_x2v[e * 97 + (c - 64)] = v2; }
    }

    // ---- MLP in 2 passes of 16 edges (union buffer) ----
    for (int p = 0; p < 2; p++) {
        const int eb0 = p * 16;
        __syncthreads();
        for (int idx = tid; idx < 16 * 128; idx += NT)
            s_un[idx] = fea_weight[(e0g + eb0) * 128 + idx];
        __syncthreads();
        #pragma unroll
        for (int it = 0; it < 4; it++) {             // h1 -> s_sig (1024)
            int o = tid + NT * it; int e = o >> 6, j = o & 63;
            float acc = fb1[j];
            const float* xe = s_un + e * 128;
            #pragma unroll 8
            for (int k = 0; k < 128; k++) acc += xe[k] * fw1[k * 64 + j];
            s_sig[o] = acc * sigmoidf_(acc);
        }
        __syncthreads();
        #pragma unroll
        for (int it = 0; it < 4; it++) {             // h2 -> s_un[2048:3072]
            int o = tid + NT * it; int e = o >> 6, j = o & 63;
            float acc = fb2[j];
            const float* xe = s_sig + e * 64;
            #pragma unroll 8
            for (int k = 0; k < 64; k++) acc += xe[k] * fw2[k * 64 + j];
            s_un[2048 + o] = acc * sigmoidf_(acc);
        }
        __syncthreads();
        #pragma unroll
        for (int it = 0; it < 6; it++) {             // w3 -> s_wout
            int o = tid + NT * it; int e = o / 96, j = o - e * 96;
            float acc = fb3[j];
            const float* xe = s_un + 2048 + e * 64;
            #pragma unroll 8
            for (int k = 0; k < 64; k++) acc += xe[k] * fw3[k * 96 + j];
            s_wout[(eb0 + e) * 96 + j] = acc;
        }
    }

    // ---- main GEMM: [sc|g] = P @ Wcat, K = 5120 in 160 chunks ----
    float aS[4][3];
    #pragma unroll
    for (int j = 0; j < 4; j++)
        #pragma unroll
        for (int c = 0; c < 3; c++) aS[j][c] = 0.f;

    float* Wc = s_un;          // [KC][96]
    float* Pc = s_un + 3072;   // [KC][32]

    for (int ci = 0; ci < 160; ci++) {
        __syncthreads();
        const int k0 = ci * KC;
        const bool ssr = (ci < 128);
        const float* baseS = ssr ? (wsss + k0 * 64) : (wvvs + (k0 - 4096) * 64);
        const float* baseG = ssr ? (wssg + k0 * 32) : (wvvg + (k0 - 4096) * 32);

        // stage W[:, 0:64]  (512 float4)
        #pragma unroll
        for (int i = 0; i < 2; i++) {
            int idx = tid + NT * i;
            int row = idx >> 4, c4 = idx & 15;
            *(float4*)(Wc + row * 96 + c4 * 4) =
                *(const float4*)(baseS + row * 64 + c4 * 4);
        }
        // stage W[:, 64:96] (256 float4)
        {
            int row = tid >> 3, c4 = tid & 7;
            *(float4*)(Wc + row * 96 + 64 + c4 * 4) =
                *(const float4*)(baseG + row * 32 + c4 * 4);
        }
        // generate P[kk][e] (1024 values)
        #pragma unroll
        for (int i = 0; i < 4; i++) {
            int idx = tid + NT * i;
            int kk = idx >> 5, e = idx & 31;
            int kg = k0 + kk;
            float p;
            if (ssr) {
                int u = kg >> 6, v = kg & 63;
                p = s_x1sT[u * 36 + e] * s_x2sT[v * 36 + e];
            } else {
                int k2 = kg - 4096;
                int u = k2 >> 5, v = k2 & 31;
                const float* av = s_x1v + e * 97 + u * 3;
                const float* bv = s_x2v + e * 97 + v * 3;
                p = INV_SQRT3_F * (av[0] * bv[0] + av[1] * bv[1] + av[2] * bv[2]);
            }
            Pc[kk * 32 + e] = p;
        }
        __syncthreads();

        const float* wp = Wc + lane;
        const float* pp = Pc + e4;
        #pragma unroll 8
        for (int kk = 0; kk < KC; kk++) {
            float4 pq = *(const float4*)(pp + kk * 32);  // 4 edges, LDS.128 broadcast
            float w0 = wp[kk * 96];
            float w1 = wp[kk * 96 + 32];
            float w2 = wp[kk * 96 + 64];
            aS[0][0] += pq.x * w0; aS[0][1] += pq.x * w1; aS[0][2] += pq.x * w2;
            aS[1][0] += pq.y * w0; aS[1][1] += pq.y * w1; aS[1][2] += pq.y * w2;
            aS[2][0] += pq.z * w0; aS[2][1] += pq.z * w1; aS[2][2] += pq.z * w2;
            aS[3][0] += pq.w * w0; aS[3][1] += pq.w * w1; aS[3][2] += pq.w * w2;
        }
    }

    // ---- sc/g epilogue ----
    #pragma unroll
    for (int j = 0; j < 4; j++) {
        int e = e4 + j;
        long base = (long)(e0g + e) * 160;
        float s;
        s = A_SC_F * aS[j][0];
        out[base + lane] = s * sigmoidf_(s) * s_wout[e * 96 + lane];
        s = A_SC_F * aS[j][1];
        out[base + lane + 32] = s * sigmoidf_(s) * s_wout[e * 96 + lane + 32];
        s_sig[e * 32 + lane] = sigmoidf_(A_SC_F * aS[j][2]);
    }

    // ---- vec: factored GEMMs, 4 edges/warp ----
    float vA[4][3];
    #pragma unroll
    for (int j = 0; j < 4; j++)
        #pragma unroll
        for (int c = 0; c < 3; c++) vA[j][c] = 0.f;

    // sv:  B1[e,v,w] = sum_u x1s[e,u]*wsvv[u,v,w];  vec += B1 * x2v[e,v,i]
    for (int vc = 0; vc < 16; vc++) {
        __syncthreads();
        int v0 = vc * 2;
        #pragma unroll
        for (int i = 0; i < 4; i++) {
            int fidx = tid + NT * i;      // [128 rows][32]: row = u*2 + vv
            int r = fidx >> 3, c4 = fidx & 7;
            int u = r >> 1, vv = r & 1;
            *(float4*)(s_un + r * 32 + c4 * 4) =
                *(const float4*)(wsvv + u * 1024 + (v0 + vv) * 32 + c4 * 4);
        }
        __syncthreads();
        float b0[4] = {0.f, 0.f, 0.f, 0.f};
        float b1[4] = {0.f, 0.f, 0.f, 0.f};
        const float* wv = s_un + lane;
        #pragma unroll 8
        for (int u = 0; u < 64; u++) {
            float4 x = *(const float4*)(s_x1sT + u * 36 + e4);
            float w0 = wv[(u * 2 + 0) * 32];
            float w1 = wv[(u * 2 + 1) * 32];
            b0[0] += x.x * w0; b0[1] += x.y * w0; b0[2] += x.z * w0; b0[3] += x.w * w0;
            b1[0] += x.x * w1; b1[1] += x.y * w1; b1[2] += x.z * w1; b1[3] += x.w * w1;
        }
        #pragma unroll
        for (int j = 0; j < 4; j++) {
            const float* xv = s_x2v + (e4 + j) * 97 + v0 * 3;
            vA[j][0] += b0[j] * xv[0] + b1[j] * xv[3];
            vA[j][1] += b0[j] * xv[1] + b1[j] * xv[4];
            vA[j][2] += b0[j] * xv[2] + b1[j] * xv[5];
        }
    }

    // vs:  B2[e,u,w] = sum_v x2s[e,v]*wvsv[u,v,w];  vec += B2 * x1v[e,u,i]
    for (int uc = 0; uc < 16; uc++) {
        __syncthreads();
        int u0 = uc * 2;
        #pragma unroll
        for (int i = 0; i < 4; i++) {
            int fidx = tid + NT * i;      // [128 rows][32]: row = uu*64 + v
            int r = fidx >> 3, c4 = fidx & 7;
            int uu = r >> 6, v = r & 63;
            *(float4*)(s_un + r * 32 + c4 * 4) =
                *(const float4*)(wvsv + (u0 + uu) * 2048 + v * 32 + c4 * 4);
        }
        __syncthreads();
        float b0[4] = {0.f, 0.f, 0.f, 0.f};
        float b1[4] = {0.f, 0.f, 0.f, 0.f};
        const float* wv = s_un + lane;
        #pragma unroll 8
        for (int v = 0; v < 64; v++) {
            float4 x = *(const float4*)(s_x2sT + v * 36 + e4);
            float w0 = wv[v * 32];
            float w1 = wv[(64 + v) * 32];
            b0[0] += x.x * w0; b0[1] += x.y * w0; b0[2] += x.z * w0; b0[3] += x.w * w0;
            b1[0] += x.x * w1; b1[1] += x.y * w1; b1[2] += x.z * w1; b1[3] += x.w * w1;
        }
        #pragma unroll
        for (int j = 0; j < 4; j++) {
            const float* xv = s_x1v + (e4 + j) * 97 + u0 * 3;
            vA[j][0] += b0[j] * xv[0] + b1[j] * xv[3];
            vA[j][1] += b0[j] * xv[1] + b1[j] * xv[4];
            vA[j][2] += b0[j] * xv[2] + b1[j] * xv[5];
        }
    }

    // ---- vec epilogue ----
    #pragma unroll
    for (int j = 0; j < 4; j++) {
        int e = e4 + j;
        float m = A_VEC_F * s_sig[e * 32 + lane] * s_wout[e * 96 + 64 + lane];
        float* o = out + (long)(e0g + e) * 160 + 64 + lane * 3;
        o[0] = vA[j][0] * m;
        o[1] = vA[j][1] * m;
        o[2] = vA[j][2] * m;
    }
}

extern "C" void kernel_launch(void* const* d_in, const int* in_sizes, int n_in,
                              void* d_out, int out_size) {
    (void)in_sizes; (void)n_in; (void)out_size;
    const float* fea_in1    = (const float*)d_in[0];
    const float* fea_in2    = (const float*)d_in[1];
    const float* fea_weight = (const float*)d_in[2];
    const float* w_ss_s     = (const float*)d_in[3];
    const float* w_vv_s     = (const float*)d_in[4];
    const float* w_ss_g     = (const float*)d_in[5];
    const float* w_vv_g     = (const float*)d_in[6];
    const float* w_sv_v     = (const float*)d_in[7];
    const float* w_vs_v     = (const float*)d_in[8];
    const float* fc_w1      = (const float*)d_in[9];
    const float* fc_b1      = (const float*)d_in[10];
    const float* fc_w2      = (const float*)d_in[11];
    const float* fc_b2      = (const float*)d_in[12];
    const float* fc_w3      = (const float*)d_in[13];
    const float* fc_b3      = (const float*)d_in[14];
    float* out = (float*)d_out;

    static int configured = 0;
    if (!configured) {
        cudaFuncSetAttribute(equiconv_kernel,
                             cudaFuncAttributeMaxDynamicSharedMemorySize,
                             SMEM_FLOATS * sizeof(float));
        cudaFuncSetAttribute(equiconv_kernel,
                             cudaFuncAttributePreferredSharedMemoryCarveout,
                             cudaSharedmemCarveoutMaxShared);
        configured = 1;
    }

    const int E = 20000;
    dim3 grid(E / TE);
    dim3 block(NT);
    equiconv_kernel<<<grid, block, SMEM_FLOATS * sizeof(float)>>>(
        fea_in1, fea_in2, fea_weight,
        w_ss_s, w_vv_s, w_ss_g, w_vv_g, w_sv_v, w_vs_v,
        fc_w1, fc_b1, fc_w2, fc_b2, fc_w3, fc_b3,
        out);
}

// round 10
// speedup vs baseline: 2.3652x; 1.0242x over previous
#include <cuda_runtime.h>
#include <cuda_bf16.h>

// EquiConv fused kernel: GEMM-restructured, 4 edges/warp, packed f32x2 FMA.
// E=20000, S=64, V=32, FC_IN=128, HID=64. out (E,160).

#define TE 32      // edges per block (20000/32 = 625 blocks exactly)
#define NT 256
#define KC 32      // K chunk

#define INV_SQRT3_F 0.5773502691896258f
#define A_SC_F 0.013975424859373686f   // 1/sqrt(64*64+32*32)
#define A_VEC_F 0.015625f              // 1/sqrt(2*64*32)

// shared layout (floats), all 16B-aligned offsets
#define OFF_X1ST 0                 // [64][36]  transposed x1s
#define OFF_X2ST 2304              // [64][36]
#define OFF_X1V  4608              // [32][97]
#define OFF_X2V  7712              // [32][97]
#define OFF_WOUT 10816             // [32][96]
#define OFF_SIG  13888             // [32][32]
#define OFF_UN   14912             // 4096 union: {MLP} / {Wc 3072 + Pc 1024} / {vec 4096}
#define SMEM_FLOATS 19008          // 76032 bytes (x3 blocks = 222.75 KiB/SM)

typedef unsigned long long u64t;

__device__ __forceinline__ float sigmoidf_(float x) {
    return __fdividef(1.0f, 1.0f + __expf(-x));
}

// splat one fp32 into both halves of an f32x2 register pair
__device__ __forceinline__ u64t splat2(float w) {
    u64t r;
    unsigned int wi = __float_as_uint(w);
    asm("mov.b64 %0, {%1, %1};" : "=l"(r) : "r"(wi));
    return r;
}
// d.lo += a.lo*b.lo ; d.hi += a.hi*b.hi   (packed fp32x2 FMA, sm_100+)
__device__ __forceinline__ void fma2(u64t& d, u64t a, u64t b) {
    asm("fma.rn.f32x2 %0, %1, %2, %0;" : "+l"(d) : "l"(a), "l"(b));
}
__device__ __forceinline__ float2 unpack2(u64t v) {
    unsigned int lo, hi;
    asm("mov.b64 {%0, %1}, %2;" : "=r"(lo), "=r"(hi) : "l"(v));
    float2 f;
    f.x = __uint_as_float(lo);
    f.y = __uint_as_float(hi);
    return f;
}

__global__ __launch_bounds__(NT, 3) void equiconv_kernel(
    const float* __restrict__ fea_in1,
    const float* __restrict__ fea_in2,
    const float* __restrict__ fea_weight,
    const float* __restrict__ wsss,   // (64,64,64)  k*64 + w   (k = u*64+v)
    const float* __restrict__ wvvs,   // (32,32,64)
    const float* __restrict__ wssg,   // (64,64,32)
    const float* __restrict__ wvvg,   // (32,32,32)
    const float* __restrict__ wsvv,   // (64,32,32)  u*1024 + v*32 + w
    const float* __restrict__ wvsv,   // (32,64,32)  u*2048 + v*32 + w
    const float* __restrict__ fw1, const float* __restrict__ fb1,
    const float* __restrict__ fw2, const float* __restrict__ fb2,
    const float* __restrict__ fw3, const float* __restrict__ fb3,
    float* __restrict__ out)
{
    extern __shared__ float smem[];
    float* s_x1sT = smem + OFF_X1ST;
    float* s_x2sT = smem + OFF_X2ST;
    float* s_x1v  = smem + OFF_X1V;
    float* s_x2v  = smem + OFF_X2V;
    float* s_wout = smem + OFF_WOUT;
    float* s_sig  = smem + OFF_SIG;
    float* s_un   = smem + OFF_UN;

    const int tid  = threadIdx.x;
    const int wid  = tid >> 5;
    const int lane = tid & 31;
    const int e4   = 4 * wid;          // warp owns edges e4..e4+3
    const int e0g  = blockIdx.x * TE;

    // ---- stage edge features (scalars transposed) ----
    for (int idx = tid; idx < TE * 160; idx += NT) {
        int e = idx / 160;
        int c = idx - e * 160;
        float v1 = fea_in1[e0g * 160 + idx];
        float v2 = fea_in2[e0g * 160 + idx];
        if (c < 64) { s_x1sT[c * 36 + e] = v1; s_x2sT[c * 36 + e] = v2; }
        else        { s_x1v[e * 97 + (c - 64)] = v1; s_x2v[e * 97 + (c - 64)] = v2; }
    }

    // ---- MLP in 2 passes of 16 edges (union buffer) ----
    for (int p = 0; p < 2; p++) {
        const int eb0 = p * 16;
        __syncthreads();
        for (int idx = tid; idx < 16 * 128; idx += NT)
            s_un[idx] = fea_weight[(e0g + eb0) * 128 + idx];
        __syncthreads();
        #pragma unroll
        for (int it = 0; it < 4; it++) {             // h1 -> s_sig (1024)
            int o = tid + NT * it; int e = o >> 6, j = o & 63;
            float acc = fb1[j];
            const float* xe = s_un + e * 128;
            #pragma unroll 8
            for (int k = 0; k < 128; k++) acc += xe[k] * fw1[k * 64 + j];
            s_sig[o] = acc * sigmoidf_(acc);
        }
        __syncthreads();
        #pragma unroll
        for (int it = 0; it < 4; it++) {             // h2 -> s_un[2048:3072]
            int o = tid + NT * it; int e = o >> 6, j = o & 63;
            float acc = fb2[j];
            const float* xe = s_sig + e * 64;
            #pragma unroll 8
            for (int k = 0; k < 64; k++) acc += xe[k] * fw2[k * 64 + j];
            s_un[2048 + o] = acc * sigmoidf_(acc);
        }
        __syncthreads();
        #pragma unroll
        for (int it = 0; it < 6; it++) {             // w3 -> s_wout
            int o = tid + NT * it; int e = o / 96, j = o - e * 96;
            float acc = fb3[j];
            const float* xe = s_un + 2048 + e * 64;
            #pragma unroll 8
            for (int k = 0; k < 64; k++) acc += xe[k] * fw3[k * 96 + j];
            s_wout[(eb0 + e) * 96 + j] = acc;
        }
    }

    // ---- main GEMM: [sc|g] = P @ Wcat, K = 5120 in 160 chunks ----
    // Packed accumulators: pair 0 = edges (e4,e4+1), pair 1 = (e4+2,e4+3);
    // 3 columns: w=lane, w=lane+32, g=lane. 0ull == {+0.f,+0.f}.
    u64t accP[2][3] = {{0ull, 0ull, 0ull}, {0ull, 0ull, 0ull}};

    float* Wc = s_un;          // [KC][96]
    float* Pc = s_un + 3072;   // [KC][32]

    for (int ci = 0; ci < 160; ci++) {
        __syncthreads();
        const int k0 = ci * KC;
        const bool ssr = (ci < 128);
        const float* baseS = ssr ? (wsss + k0 * 64) : (wvvs + (k0 - 4096) * 64);
        const float* baseG = ssr ? (wssg + k0 * 32) : (wvvg + (k0 - 4096) * 32);

        // stage W[:, 0:64]  (512 float4)
        #pragma unroll
        for (int i = 0; i < 2; i++) {
            int idx = tid + NT * i;
            int row = idx >> 4, c4 = idx & 15;
            *(float4*)(Wc + row * 96 + c4 * 4) =
                *(const float4*)(baseS + row * 64 + c4 * 4);
        }
        // stage W[:, 64:96] (256 float4)
        {
            int row = tid >> 3, c4 = tid & 7;
            *(float4*)(Wc + row * 96 + 64 + c4 * 4) =
                *(const float4*)(baseG + row * 32 + c4 * 4);
        }
        // generate P[kk][e] (1024 values)
        #pragma unroll
        for (int i = 0; i < 4; i++) {
            int idx = tid + NT * i;
            int kk = idx >> 5, e = idx & 31;
            int kg = k0 + kk;
            float p;
            if (ssr) {
                int u = kg >> 6, v = kg & 63;
                p = s_x1sT[u * 36 + e] * s_x2sT[v * 36 + e];
            } else {
                int k2 = kg - 4096;
                int u = k2 >> 5, v = k2 & 31;
                const float* av = s_x1v + e * 97 + u * 3;
                const float* bv = s_x2v + e * 97 + v * 3;
                p = INV_SQRT3_F * (av[0] * bv[0] + av[1] * bv[1] + av[2] * bv[2]);
            }
            Pc[kk * 32 + e] = p;
        }
        __syncthreads();

        const float* wp = Wc + lane;
        const float* pp = Pc + e4;
        #pragma unroll 8
        for (int kk = 0; kk < KC; kk++) {
            // LDS.128 broadcast: 4 edges = 2 packed f32x2 pairs, no pack needed
            ulonglong2 pq = *(const ulonglong2*)(pp + kk * 32);
            u64t w0 = splat2(wp[kk * 96]);
            u64t w1 = splat2(wp[kk * 96 + 32]);
            u64t w2 = splat2(wp[kk * 96 + 64]);
            fma2(accP[0][0], pq.x, w0);
            fma2(accP[0][1], pq.x, w1);
            fma2(accP[0][2], pq.x, w2);
            fma2(accP[1][0], pq.y, w0);
            fma2(accP[1][1], pq.y, w1);
            fma2(accP[1][2], pq.y, w2);
        }
    }

    // ---- sc/g epilogue ----
    #pragma unroll
    for (int pr = 0; pr < 2; pr++) {
        float2 c0 = unpack2(accP[pr][0]);
        float2 c1 = unpack2(accP[pr][1]);
        float2 c2 = unpack2(accP[pr][2]);
        #pragma unroll
        for (int h = 0; h < 2; h++) {
            int e = e4 + 2 * pr + h;
            long base = (long)(e0g + e) * 160;
            float a0 = h ? c0.y : c0.x;
            float a1 = h ? c1.y : c1.x;
            float a2 = h ? c2.y : c2.x;
            float s;
            s = A_SC_F * a0;
            out[base + lane] = s * sigmoidf_(s) * s_wout[e * 96 + lane];
            s = A_SC_F * a1;
            out[base + lane + 32] = s * sigmoidf_(s) * s_wout[e * 96 + lane + 32];
            s_sig[e * 32 + lane] = sigmoidf_(A_SC_F * a2);
        }
    }

    // ---- vec: factored GEMMs, 4 edges/warp, packed f32x2 ----
    float vA[4][3];
    #pragma unroll
    for (int j = 0; j < 4; j++)
        #pragma unroll
        for (int c = 0; c < 3; c++) vA[j][c] = 0.f;

    // sv:  B1[e,v,w] = sum_u x1s[e,u]*wsvv[u,v,w];  vec += B1 * x2v[e,v,i]
    for (int vc = 0; vc < 16; vc++) {
        __syncthreads();
        int v0 = vc * 2;
        #pragma unroll
        for (int i = 0; i < 4; i++) {
            int fidx = tid + NT * i;      // [128 rows][32]: row = u*2 + vv
            int r = fidx >> 3, c4 = fidx & 7;
            int u = r >> 1, vv = r & 1;
            *(float4*)(s_un + r * 32 + c4 * 4) =
                *(const float4*)(wsvv + u * 1024 + (v0 + vv) * 32 + c4 * 4);
        }
        __syncthreads();
        u64t b0p[2] = {0ull, 0ull};
        u64t b1p[2] = {0ull, 0ull};
        const float* wv = s_un + lane;
        #pragma unroll 8
        for (int u = 0; u < 64; u++) {
            ulonglong2 x = *(const ulonglong2*)(s_x1sT + u * 36 + e4);
            u64t w0 = splat2(wv[(u * 2 + 0) * 32]);
            u64t w1 = splat2(wv[(u * 2 + 1) * 32]);
            fma2(b0p[0], x.x, w0); fma2(b0p[1], x.y, w0);
            fma2(b1p[0], x.x, w1); fma2(b1p[1], x.y, w1);
        }
        float2 b0a = unpack2(b0p[0]), b0b = unpack2(b0p[1]);
        float2 b1a = unpack2(b1p[0]), b1b = unpack2(b1p[1]);
        float b0[4] = {b0a.x, b0a.y, b0b.x, b0b.y};
        float b1[4] = {b1a.x, b1a.y, b1b.x, b1b.y};
        #pragma unroll
        for (int j = 0; j < 4; j++) {
            const float* xv = s_x2v + (e4 + j) * 97 + v0 * 3;
            vA[j][0] += b0[j] * xv[0] + b1[j] * xv[3];
            vA[j][1] += b0[j] * xv[1] + b1[j] * xv[4];
            vA[j][2] += b0[j] * xv[2] + b1[j] * xv[5];
        }
    }

    // vs:  B2[e,u,w] = sum_v x2s[e,v]*wvsv[u,v,w];  vec += B2 * x1v[e,u,i]
    for (int uc = 0; uc < 16; uc++) {
        __syncthreads();
        int u0 = uc * 2;
        #pragma unroll
        for (int i = 0; i < 4; i++) {
            int fidx = tid + NT * i;      // [128 rows][32]: row = uu*64 + v
            int r = fidx >> 3, c4 = fidx & 7;
            int uu = r >> 6, v = r & 63;
            *(float4*)(s_un + r * 32 + c4 * 4) =
                *(const float4*)(wvsv + (u0 + uu) * 2048 + v * 32 + c4 * 4);
        }
        __syncthreads();
        u64t b0p[2] = {0ull, 0ull};
        u64t b1p[2] = {0ull, 0ull};
        const float* wv = s_un + lane;
        #pragma unroll 8
        for (int v = 0; v < 64; v++) {
            ulonglong2 x = *(const ulonglong2*)(s_x2sT + v * 36 + e4);
            u64t w0 = splat2(wv[v * 32]);
            u64t w1 = splat2(wv[(64 + v) * 32]);
            fma2(b0p[0], x.x, w0); fma2(b0p[1], x.y, w0);
            fma2(b1p[0], x.x, w1); fma2(b1p[1], x.y, w1);
        }
        float2 b0a = unpack2(b0p[0]), b0b = unpack2(b0p[1]);
        float2 b1a = unpack2(b1p[0]), b1b = unpack2(b1p[1]);
        float b0[4] = {b0a.x, b0a.y, b0b.x, b0b.y};
        float b1[4] = {b1a.x, b1a.y, b1b.x, b1b.y};
        #pragma unroll
        for (int j = 0; j < 4; j++) {
            const float* xv = s_x1v + (e4 + j) * 97 + u0 * 3;
            vA[j][0] += b0[j] * xv[0] + b1[j] * xv[3];
            vA[j][1] += b0[j] * xv[1] + b1[j] * xv[4];
            vA[j][2] += b0[j] * xv[2] + b1[j] * xv[5];
        }
    }

    // ---- vec epilogue ----
    #pragma unroll
    for (int j = 0; j < 4; j++) {
        int e = e4 + j;
        float m = A_VEC_F * s_sig[e * 32 + lane] * s_wout[e * 96 + 64 + lane];
        float* o = out + (long)(e0g + e) * 160 + 64 + lane * 3;
        o[0] = vA[j][0] * m;
        o[1] = vA[j][1] * m;
        o[2] = vA[j][2] * m;
    }
}

extern "C" void kernel_launch(void* const* d_in, const int* in_sizes, int n_in,
                              void* d_out, int out_size) {
    (void)in_sizes; (void)n_in; (void)out_size;
    const float* fea_in1    = (const float*)d_in[0];
    const float* fea_in2    = (const float*)d_in[1];
    const float* fea_weight = (const float*)d_in[2];
    const float* w_ss_s     = (const float*)d_in[3];
    const float* w_vv_s     = (const float*)d_in[4];
    const float* w_ss_g     = (const float*)d_in[5];
    const float* w_vv_g     = (const float*)d_in[6];
    const float* w_sv_v     = (const float*)d_in[7];
    const float* w_vs_v     = (const float*)d_in[8];
    const float* fc_w1      = (const float*)d_in[9];
    const float* fc_b1      = (const float*)d_in[10];
    const float* fc_w2      = (const float*)d_in[11];
    const float* fc_b2      = (const float*)d_in[12];
    const float* fc_w3      = (const float*)d_in[13];
    const float* fc_b3      = (const float*)d_in[14];
    float* out = (float*)d_out;

    static int configured = 0;
    if (!configured) {
        cudaFuncSetAttribute(equiconv_kernel,
                             cudaFuncAttributeMaxDynamicSharedMemorySize,
                             SMEM_FLOATS * sizeof(float));
        cudaFuncSetAttribute(equiconv_kernel,
                             cudaFuncAttributePreferredSharedMemoryCarveout,
                             cudaSharedmemCarveoutMaxShared);
        configured = 1;
    }

    const int E = 20000;
    dim3 grid(E / TE);
    dim3 block(NT);
    equiconv_kernel<<<grid, block, SMEM_FLOATS * sizeof(float)>>>(
        fea_in1, fea_in2, fea_weight,
        w_ss_s, w_vv_s, w_ss_g, w_vv_g, w_sv_v, w_vs_v,
        fc_w1, fc_b1, fc_w2, fc_b2, fc_w3, fc_b3,
        out);
}